// round 7
// baseline (speedup 1.0000x reference)
#include <cuda_runtime.h>
#include <cuda_bf16.h>
#include <cstdint>

// MaxUnpooling2D scatter-add, pipelined at half-INPUT granularity:
//   step s: scatter input-half (b=s/2, h=s&1) into batch b's full 64MB slice
//           (unpredicated, single pass over the stream)
//        || zero the 32MB half-region consumed at step s+2.
// L2 working set: 64MB scatter target + 32MB zero target = 96MB < 126MB L2,
// so atomics stay L2-resident (R3's 128MB variant thrashed; this fits).
// Prologue zeroes batch 0's two halves. Atomic message rate (~150G/s LTS
// ceiling) is the floor; everything else is arranged to hide under it.

static constexpr int B         = 8;
static constexpr int IN_PER_B  = 1 << 22;      // elems per batch input
static constexpr int HALF_IN   = IN_PER_B / 2; // 2^21 elems, 8 MB f32
static constexpr int OUT_PER_B = 1 << 24;      // elems per batch output
static constexpr int HALF_OUT  = OUT_PER_B / 2;// 2^23 elems, 32 MB

static constexpr int SCATTER_BLOCKS   = (HALF_IN / 4) / 256;   // 2048
static constexpr int ZERO_HALF_BLOCKS = (HALF_OUT / 4) / 256;  // 8192

__global__ void __launch_bounds__(256)
zero_kernel(float4* __restrict__ out4)
{
    int i = blockIdx.x * blockDim.x + threadIdx.x;
    out4[i] = make_float4(0.f, 0.f, 0.f, 0.f);
}

// Blocks [0, SCATTER_BLOCKS): unpredicated scatter of one input half.
// Blocks [SCATTER_BLOCKS, +ZERO_HALF_BLOCKS): zero a 32MB half-region.
__global__ void __launch_bounds__(256)
pipe_kernel(const float4* __restrict__ vals4,   // input half base
            const int4*  __restrict__ idx4,
            float* __restrict__ out_scatter,    // batch output base
            float4* __restrict__ out_zero)      // 32MB region or nullptr
{
    int bid = blockIdx.x;
    if (bid < SCATTER_BLOCKS) {
        int i = bid * 256 + threadIdx.x;
        float4 v = __ldcs(vals4 + i);
        int4   x = __ldcs(idx4 + i);
        atomicAdd(out_scatter + x.x, v.x);
        atomicAdd(out_scatter + x.y, v.y);
        atomicAdd(out_scatter + x.z, v.z);
        atomicAdd(out_scatter + x.w, v.w);
    } else {
        int i = (bid - SCATTER_BLOCKS) * 256 + threadIdx.x;
        out_zero[i] = make_float4(0.f, 0.f, 0.f, 0.f);
    }
}

extern "C" void kernel_launch(void* const* d_in, const int* in_sizes, int n_in,
                              void* d_out, int out_size)
{
    const float* vals = (const float*)d_in[0];
    const int*   idx  = (const int*)d_in[1];
    float* out = (float*)d_out;

    // Prologue: zero batch 0 entirely (regions 0 and 1).
    zero_kernel<<<2 * ZERO_HALF_BLOCKS, 256>>>((float4*)out);

    // 16 steps: step s scatters input half s, zeroes half-region s+2.
    for (int s = 0; s < 2 * B; s++) {
        int b = s >> 1;
        int h = s & 1;
        const float4* v4 = (const float4*)(vals + (size_t)b * IN_PER_B
                                                + (size_t)h * HALF_IN);
        const int4* x4 = (const int4*)(idx + (size_t)b * IN_PER_B
                                           + (size_t)h * HALF_IN);
        float* out_b = out + (size_t)b * OUT_PER_B;

        if (s + 2 < 2 * B) {
            float4* zdst = (float4*)(out + (size_t)(s + 2) * HALF_OUT);
            pipe_kernel<<<SCATTER_BLOCKS + ZERO_HALF_BLOCKS, 256>>>(
                v4, x4, out_b, zdst);
        } else {
            pipe_kernel<<<SCATTER_BLOCKS, 256>>>(v4, x4, out_b, nullptr);
        }
    }
}

// round 8
// speedup vs baseline: 1.4979x; 1.4979x over previous
#include <cuda_runtime.h>
#include <cuda_bf16.h>
#include <cstdint>

// MaxUnpooling2D scatter-add — R5 topology (the proven one), tuned.
//   step s (0..15): scatter phase h=(s&1) of batch b=(s>>1) into its 32MB
//                   output half  ||  zero the 32MB half needed at step s+1.
// L2 working set per step: 32MB scatter target + 32MB zero target + 32MB
// val/idx stream = 96MB < 126MB, so the stream's 2nd pass (other phase) hits
// L2 -> loads use default policy (NOT __ldcs, which evicted the stream in R5
// and forced 134MB of redundant DRAM reads).
// Atomic-message rate (~150G msg/s) is the floor; predicated-off RED lanes
// are free (cost is per active lane), so phase predication wastes ~nothing.

static constexpr int B         = 8;
static constexpr int IN_PER_B  = 1 << 22;        // elems per batch input
static constexpr int OUT_PER_B = 1 << 24;        // elems per batch output
static constexpr int HALF_OUT  = OUT_PER_B / 2;  // 2^23 elems, 32 MB

// scatter: 2 vec4 per thread -> 4.19M elems / (256*8) = 2048 blocks
static constexpr int SCATTER_BLOCKS = IN_PER_B / (256 * 8);   // 2048
// zero: 2 vec4 per thread -> 8.39M elems / (256*8) = 4096 blocks
static constexpr int ZERO_BLOCKS    = HALF_OUT / (256 * 8);   // 4096

__global__ void __launch_bounds__(256)
zero_half_kernel(float4* __restrict__ out4)
{
    int i = (blockIdx.x * 256 + threadIdx.x) * 2;
    float4 z = make_float4(0.f, 0.f, 0.f, 0.f);
    out4[i]     = z;
    out4[i + 1] = z;
}

// Blocks [0, SCATTER_BLOCKS): scatter phase `phase` (8 elems/thread).
// Blocks [SCATTER_BLOCKS, +ZERO_BLOCKS): zero next 32MB half (8 elems/thread).
__global__ void __launch_bounds__(256)
pipe_half_kernel(const float4* __restrict__ vals4,
                 const int4*  __restrict__ idx4,
                 float* __restrict__ out_scatter,  // batch output base
                 int phase,                        // 0: idx<2^23, 1: >=
                 float4* __restrict__ out_zero)    // 32MB region or nullptr
{
    int bid = blockIdx.x;
    if (bid < SCATTER_BLOCKS) {
        int i = (bid * 256 + threadIdx.x) * 2;
        // Front-batch all 4 loads (MLP=4) before any RED.
        float4 v0 = vals4[i];
        float4 v1 = vals4[i + 1];
        int4   x0 = idx4[i];
        int4   x1 = idx4[i + 1];
        if ((x0.x >> 23) == phase) atomicAdd(out_scatter + x0.x, v0.x);
        if ((x0.y >> 23) == phase) atomicAdd(out_scatter + x0.y, v0.y);
        if ((x0.z >> 23) == phase) atomicAdd(out_scatter + x0.z, v0.z);
        if ((x0.w >> 23) == phase) atomicAdd(out_scatter + x0.w, v0.w);
        if ((x1.x >> 23) == phase) atomicAdd(out_scatter + x1.x, v1.x);
        if ((x1.y >> 23) == phase) atomicAdd(out_scatter + x1.y, v1.y);
        if ((x1.z >> 23) == phase) atomicAdd(out_scatter + x1.z, v1.z);
        if ((x1.w >> 23) == phase) atomicAdd(out_scatter + x1.w, v1.w);
    } else {
        int i = ((bid - SCATTER_BLOCKS) * 256 + threadIdx.x) * 2;
        float4 z = make_float4(0.f, 0.f, 0.f, 0.f);
        out_zero[i]     = z;
        out_zero[i + 1] = z;
    }
}

extern "C" void kernel_launch(void* const* d_in, const int* in_sizes, int n_in,
                              void* d_out, int out_size)
{
    const float* vals = (const float*)d_in[0];
    const int*   idx  = (const int*)d_in[1];
    float* out = (float*)d_out;

    // Prologue: zero batch 0, half 0.
    zero_half_kernel<<<ZERO_BLOCKS, 256>>>((float4*)out);

    // 16 half-steps: step s scatters (b=s>>1, phase=s&1), zeroes region s+1.
    for (int s = 0; s < 2 * B; s++) {
        int b = s >> 1;
        int h = s & 1;
        const float4* v4 = (const float4*)(vals + (size_t)b * IN_PER_B);
        const int4*   x4 = (const int4*)(idx + (size_t)b * IN_PER_B);
        float* out_b = out + (size_t)b * OUT_PER_B;

        if (s + 1 < 2 * B) {
            float4* zdst = (float4*)(out + (size_t)(s + 1) * HALF_OUT);
            pipe_half_kernel<<<SCATTER_BLOCKS + ZERO_BLOCKS, 256>>>(
                v4, x4, out_b, h, zdst);
        } else {
            pipe_half_kernel<<<SCATTER_BLOCKS, 256>>>(v4, x4, out_b, h, nullptr);
        }
    }
}